// round 14
// baseline (speedup 1.0000x reference)
#include <cuda_runtime.h>
#include <cstdint>

// ---------------- problem constants ----------------
#define B_TOT   4096
#define K1      30
#define K2      80
#define NT      7
#define NTILE   49          // 7*7
#define TPI     1470        // K1*NTILE tiles per image
#define C2N     1280        // K2*16
#define ETA_PER_B 13230     // TPI*9

// output layout: x_rec | mean | log_var | eta  (flat f32, tuple order)
#define OUT_XREC 0ull
#define OUT_MEAN 3211264ull
#define OUT_LV   8454144ull
#define OUT_ETA  13697024ull

// ---------------- threefry2x32 (JAX-exact) ----------------
#ifdef __CUDA_ARCH__
#define TF_ROT(x, r) __funnelshift_l((x), (x), (r))
#else
#define TF_ROT(x, r) (((x) << (r)) | ((x) >> (32 - (r))))
#endif

__host__ __device__ inline void tf2x32(uint32_t k0, uint32_t k1,
                                       uint32_t x0, uint32_t x1,
                                       uint32_t& o0, uint32_t& o1) {
    uint32_t ks2 = k0 ^ k1 ^ 0x1BD11BDAu;
    x0 += k0; x1 += k1;
#define TF_RND(r) { x0 += x1; x1 = TF_ROT(x1, r); x1 ^= x0; }
    TF_RND(13) TF_RND(15) TF_RND(26) TF_RND(6)
    x0 += k1;  x1 += ks2 + 1u;
    TF_RND(17) TF_RND(29) TF_RND(16) TF_RND(24)
    x0 += ks2; x1 += k0 + 2u;
    TF_RND(13) TF_RND(15) TF_RND(26) TF_RND(6)
    x0 += k0;  x1 += k1 + 3u;
    TF_RND(17) TF_RND(29) TF_RND(16) TF_RND(24)
    x0 += k1;  x1 += ks2 + 4u;
    TF_RND(13) TF_RND(15) TF_RND(26) TF_RND(6)
    x0 += ks2; x1 += k0 + 5u;
#undef TF_RND
    o0 = x0; o1 = x1;
}

// partitionable-mode 32-bit bits: counter = 64-bit idx (hi=0), out = o0 ^ o1.
__device__ __forceinline__ uint32_t tf_bits(uint32_t k0, uint32_t k1, uint32_t idx) {
    uint32_t a, b;
    tf2x32(k0, k1, 0u, idx, a, b);
    return a ^ b;
}

__device__ __forceinline__ float bits_to_f01(uint32_t b) {
    return __uint_as_float((b >> 9) | 0x3F800000u) - 1.0f;   // [0,1)
}
// categorical score denominator: w = -log(u) > 0, u clamped away from 0 like JAX
__device__ __forceinline__ float neglogu(uint32_t b) {
    const float TINY = 1.17549435e-38f;
    float f = bits_to_f01(b);
    float u = f + TINY;
    u = fmaxf(TINY, u);
    return -__logf(u);
}
__device__ __forceinline__ float normalf(uint32_t b) {
    const float LO = -0.99999994f;   // nextafter(-1, 0)
    float f = bits_to_f01(b);
    float u = fmaf(f, 2.0f, LO);     // (hi-lo) rounds to exactly 2.0f; f*2 exact
    u = fmaxf(LO, u);
    return 1.41421356237f * erfinvf(u);
}

// constant-index component selectors (fold to direct register reads)
#define F4C(Q, i) ((i)==0 ? (Q).x : (i)==1 ? (Q).y : (i)==2 ? (Q).z : (Q).w)
#define RBV(rs, i) ((i) < 4 ? F4C(rb[rs][0], (i)) : \
                    (i) < 8 ? F4C(rb[rs][1], (i)-4) : F4C(rb[rs][2], (i)-8))
#define WVAL(v) ((v) < 4 ? F4C(wa, (v)) : F4C(wb, (v)-4))

// ---------------- pool MLP: eta -> smem staging, UNNORMALIZED lg in regs ----
// w1p/w2p are 9x12 padded (row o at o*12, cols 9..11 zero), 16B-aligned.
// FMA order per output: tt ascending -> bit-identical to previous rounds.
__device__ __forceinline__ void pool_mlp(const float t[9],
                                         const float* __restrict__ w1p,
                                         const float* __restrict__ w2p,
                                         float* __restrict__ eta_stg,  // smem
                                         float lg[9]) {
    float h1[9];
    const float4* w1q = (const float4*)w1p;
#pragma unroll
    for (int o = 0; o < 9; o++) {
        float4 A = w1q[o * 3 + 0];
        float4 B = w1q[o * 3 + 1];
        float  c8 = w1p[o * 12 + 8];
        float a = 0.f;
        a += t[0] * A.x; a += t[1] * A.y; a += t[2] * A.z; a += t[3] * A.w;
        a += t[4] * B.x; a += t[5] * B.y; a += t[6] * B.z; a += t[7] * B.w;
        a += t[8] * c8;
        h1[o] = tanhf(a);
    }
    float mx = -3.402823466e38f;
    const float4* w2q = (const float4*)w2p;
#pragma unroll
    for (int o = 0; o < 9; o++) {
        float4 A = w2q[o * 3 + 0];
        float4 B = w2q[o * 3 + 1];
        float  c8 = w2p[o * 12 + 8];
        float a = 0.f;
        a += h1[0] * A.x; a += h1[1] * A.y; a += h1[2] * A.z; a += h1[3] * A.w;
        a += h1[4] * B.x; a += h1[5] * B.y; a += h1[6] * B.z; a += h1[7] * B.w;
        a += h1[8] * c8;
        lg[o] = a; mx = fmaxf(mx, a);
    }
    float s = 0.f;
#pragma unroll
    for (int o = 0; o < 9; o++) { lg[o] = __expf(lg[o] - mx); s += lg[o]; }
    float inv = 1.0f / s;
#pragma unroll
    for (int o = 0; o < 9; o++) eta_stg[o] = lg[o] * inv;
}

// ---------------- ONE fused kernel: whole pipeline per image ----------------
__global__ __launch_bounds__(256) void k_fused(
    const float* __restrict__ x,
    const float* __restrict__ enc1_w,
    const float* __restrict__ pw1, const float* __restrict__ pw2,
    const float* __restrict__ enc2_w,
    const float* __restrict__ h_w,  const float* __restrict__ h_b,
    const float* __restrict__ mean_w, const float* __restrict__ mean_b,
    const float* __restrict__ lv_w,   const float* __restrict__ lv_b,
    const float* __restrict__ dec2_w, const float* __restrict__ dec1_w,
    const float* __restrict__ alpha_p,
    float* __restrict__ out,
    uint32_t kp0, uint32_t kp1, uint32_t ku0, uint32_t ku1,
    uint32_t kc0, uint32_t kc1, uint32_t kn0, uint32_t kn1)
{
    // 4 shifted copies of the 28x28 input, row stride 36 (16B-aligned rows,
    // conflict-free LDS.128 for consecutive-m lanes). copy s holds col j at
    // index j+s, so tile col x0=3m is 16B-aligned in copy s = m&3.
    __shared__ __align__(16) float xs4[4 * 28 * 36];
    __shared__ __align__(16) float ws[K1 * 64];   // enc1_w stage 1, dec1_w stage 4
    __shared__ __align__(16) float w1p[108], w2p[108];  // 9x12 padded pool weights
    __shared__ __align__(16) float pooled[TPI];   // stage-1 out, reused as s2
    __shared__ __align__(16) float scratch[2560]; // stage1 eta staging (2304);
                                                  // later flat=scratch, hsm=+1280
    __shared__ unsigned short pyx[TPI];  // packed (py<<8)|px absolute unpool coord

    float* flat = scratch;
    float* hsm  = scratch + 1280;

    int b = blockIdx.x, tid = threadIdx.x;

    for (int i = tid; i < 784; i += 256) {
        float v = x[(size_t)b * 784 + i];
        int y = i / 28, c = i % 28;
        int base = y * 36 + c;
        xs4[base]                = v;
        xs4[28 * 36 + base + 1]  = v;
        xs4[2 * 28 * 36 + base + 2] = v;
        xs4[3 * 28 * 36 + base + 3] = v;
    }
    for (int i = tid; i < K1 * 64; i += 256) ws[i] = enc1_w[i];
    if (tid < 216) {
        int mat = tid / 108, idx = tid % 108;
        int row = idx / 12, col = idx % 12;
        float v = (col < 9) ? (mat ? pw2[row * 9 + col] : pw1[row * 9 + col]) : 0.f;
        (mat ? w2p : w1p)[idx] = v;
    }
    __syncthreads();

    // ===== stage 1: enc1 conv + pool MLP + eta (staged) + 2x categorical =====
    // 6 rounds of 256 tiles; eta staged in smem then flushed coalesced.
#pragma unroll 1
    for (int round = 0; round < 6; round++) {
        int w = round * 256 + tid;
        if (w < TPI) {
            int c = w / NTILE, nm = w % NTILE;
            int n = nm / NT, m = nm % NT;
            int y0 = 3 * n, x0 = 3 * m;
            const float* wc = &ws[c * 64];

            int s = m & 3;
            const float* xbase = &xs4[(s * 28 + y0) * 36 + x0 + s];

            float t[9];
#pragma unroll
            for (int i = 0; i < 9; i++) t[i] = 0.f;

            // rolling 3-row window; each input row & weight row loaded ONCE.
            float4 rb[3][3];
#define LOADROW(slot, r) { const float4* p = (const float4*)(xbase + (r) * 36); \
                           rb[slot][0] = p[0]; rb[slot][1] = p[1]; rb[slot][2] = p[2]; }
            LOADROW(0, 0)
            LOADROW(1, 1)
#pragma unroll
            for (int u = 0; u < 8; u++) {
                LOADROW((u + 2) % 3, u + 2)
                const float4* wr = (const float4*)&wc[u * 8];
                float4 wa = wr[0], wb = wr[1];
#pragma unroll
                for (int ty = 0; ty < 3; ty++) {
                    int rs = (u + ty) % 3;
#pragma unroll
                    for (int v = 0; v < 8; v++) {
                        float wv = WVAL(v);
                        // per-output order: u asc, v asc (bit-identical)
                        t[ty * 3 + 0] += RBV(rs, v + 0) * wv;
                        t[ty * 3 + 1] += RBV(rs, v + 1) * wv;
                        t[ty * 3 + 2] += RBV(rs, v + 2) * wv;
                    }
                }
            }
#undef LOADROW

            float lg[9];
            pool_mlp(t, w1p, w2p, &scratch[tid * 9], lg);

            uint32_t e0 = (uint32_t)b * (uint32_t)ETA_PER_B + (uint32_t)w * 9u;

            // argmax of lg_t / w_t via cross-multiplication (no divisions)
            float wp0 = neglogu(tf_bits(kp0, kp1, e0));
            float wu0 = neglogu(tf_bits(ku0, ku1, e0));
            float bnp = lg[0], bdp = wp0, pv = t[0];
            float bnu = lg[0], bdu = wu0;
            int z2 = 0;
#pragma unroll
            for (int tt = 1; tt < 9; tt++) {
                float wp = neglogu(tf_bits(kp0, kp1, e0 + tt));
                if (lg[tt] * bdp > bnp * wp) { bnp = lg[tt]; bdp = wp; pv = t[tt]; }
                float wu = neglogu(tf_bits(ku0, ku1, e0 + tt));
                if (lg[tt] * bdu > bnu * wu) { bnu = lg[tt]; bdu = wu; z2 = tt; }
            }
            pooled[w] = pv;
            pyx[w] = (unsigned short)(((y0 + z2 / 3) << 8) | (x0 + z2 % 3));
        }
        __syncthreads();
        // coalesced eta flush for this round (float2: base is always even)
        {
            int cnt2 = ((round < 5) ? 2304 : 1710) / 2;
            size_t base = OUT_ETA + (size_t)b * ETA_PER_B + (size_t)round * 2304;
            const float2* src = (const float2*)scratch;
            float2* dst = (float2*)&out[base];
            for (int i = tid; i < cnt2; i += 256) dst[i] = src[i];
        }
        __syncthreads();
    }

    // overlap: start loading dec1_w into ws (used only in stage 4; barriers
    // at the 2a/2b/2c/3 boundaries guarantee completion before use)
    for (int i = tid; i < K1 * 64; i += 256) ws[i] = dec1_w[i];

    // ===== stage 2a: conv2 -> flat (thread = (k5, ij), 256 exact, 5 accs) =====
    {
        int k5 = tid / 16, ij = tid % 16;
        int ii = ij / 4, jj = ij % 4;
        float acc[5];
#pragma unroll
        for (int g = 0; g < 5; g++) acc[g] = 0.f;
        for (int c = 0; c < K1; c++) {
            float pv[16];
            const float* pc = &pooled[c * NTILE + ii * NT + jj];
#pragma unroll
            for (int u = 0; u < 4; u++)
#pragma unroll
                for (int v = 0; v < 4; v++) pv[u * 4 + v] = pc[u * NT + v];
#pragma unroll
            for (int g = 0; g < 5; g++) {
                const float4* wk4 = (const float4*)&enc2_w[((k5 * 5 + g) * K1 + c) * 16];
                float a = acc[g];
#pragma unroll
                for (int u = 0; u < 4; u++) {
                    float4 wv = wk4[u];
                    a += pv[u * 4 + 0] * wv.x;
                    a += pv[u * 4 + 1] * wv.y;
                    a += pv[u * 4 + 2] * wv.z;
                    a += pv[u * 4 + 3] * wv.w;
                }
                acc[g] = a;
            }
        }
#pragma unroll
        for (int g = 0; g < 5; g++)
            flat[(k5 * 5 + g) * 16 + ij] = acc[g];
    }
    __syncthreads();

    // ===== stage 2b: h = tanh(flat @ h_w^T + h_b) =====
    for (int r = tid; r < C2N; r += 256) {
        int k = r / 16;
        const float4* wr4 = (const float4*)&h_w[r * 16];
        const float4* fr4 = (const float4*)&flat[k * 16];
        float a = h_b[r];
#pragma unroll
        for (int q = 0; q < 4; q++) {
            float4 fv = fr4[q], wv = wr4[q];
            a += fv.x * wv.x; a += fv.y * wv.y;
            a += fv.z * wv.z; a += fv.w * wv.w;
        }
        hsm[r] = tanhf(a);
    }
    __syncthreads();

    // ===== stage 2c: mean / logvar + reparam sample (s -> flat) =====
    for (int r = tid; r < C2N; r += 256) {
        int k = r / 16;
        const float4* wm4 = (const float4*)&mean_w[r * 16];
        const float4* wl4 = (const float4*)&lv_w[r * 16];
        const float4* h4  = (const float4*)&hsm[k * 16];
        float m0 = mean_b[r], l0 = lv_b[r];
#pragma unroll
        for (int q = 0; q < 4; q++) {
            float4 hv = h4[q], wmv = wm4[q], wlv = wl4[q];
            m0 += hv.x * wmv.x; l0 += hv.x * wlv.x;
            m0 += hv.y * wmv.y; l0 += hv.y * wlv.y;
            m0 += hv.z * wmv.z; l0 += hv.z * wlv.z;
            m0 += hv.w * wmv.w; l0 += hv.w * wlv.w;
        }
        out[OUT_MEAN + (size_t)b * C2N + r] = m0;
        out[OUT_LV   + (size_t)b * C2N + r] = l0;

        uint32_t e = (uint32_t)b * (uint32_t)C2N + (uint32_t)r;
        flat[r] = m0 + __expf(0.5f * l0) * normalf(tf_bits(kc0, kc1, e));
    }
    __syncthreads();

    // ===== stage 3: dec2 transposed conv (s=flat -> s2=pooled) =====
    if (tid < K1 * NT) {                 // 210 threads: (c1, y), 7 outputs each
        int c1 = tid / NT, y = tid % NT;
        int ilo = max(0, y - 3), ihi = min(3, y);
        float acc[7];
#pragma unroll
        for (int i = 0; i < 7; i++) acc[i] = 0.f;
        for (int c2 = 0; c2 < K2; c2++) {
            const float4* s4 = (const float4*)&flat[c2 * 16];
            const float4* w4 = (const float4*)&dec2_w[(c2 * K1 + c1) * 16];
            for (int i = ilo; i <= ihi; i++) {
                float4 sv4 = s4[i];
                float4 wv4 = w4[y - i];
                float sv[4] = {sv4.x, sv4.y, sv4.z, sv4.w};
                float wv[4] = {wv4.x, wv4.y, wv4.z, wv4.w};
#pragma unroll
                for (int j = 0; j < 4; j++)
#pragma unroll
                    for (int v = 0; v < 4; v++)
                        acc[j + v] += sv[j] * wv[v];
            }
        }
#pragma unroll
        for (int xx = 0; xx < 7; xx++)
            pooled[c1 * NTILE + y * NT + xx] = acc[xx];
    }
    __syncthreads();

    // ===== stage 4: unpool + dec1 transposed conv + diag noise =====
    // thread = one row-quad of 4 consecutive pixels (28 rows x 7 quads = 196)
    if (tid < 196) {
        int y  = tid / 7;
        int x0 = (tid % 7) * 4;
        int nlo = (y  >= 9) ? (y  - 7) / 3 : 0;
        int nhi = min(6, y / 3);
        int mlo = (x0 >= 9) ? (x0 - 7) / 3 : 0;
        int mhi = min(6, (x0 + 3) / 3);
        float a0 = 0.f, a1 = 0.f, a2 = 0.f, a3 = 0.f;
        for (int c = 0; c < K1; c++) {
            int cb = c * NTILE;
            const float* wc = &ws[c * 64];
            for (int n = nlo; n <= nhi; n++) {
                int rb2 = cb + n * NT;
                for (int m = mlo; m <= mhi; m++) {
                    int idx = rb2 + m;
                    unsigned int pp = pyx[idx];
                    int uu = y - (int)(pp >> 8);
                    if ((unsigned)uu < 8u) {
                        float sv = pooled[idx];
                        const float* wr = &wc[uu * 8];
                        int vb = x0 - (int)(pp & 0xFFu);
                        if ((unsigned)(vb + 0) < 8u) a0 += sv * wr[vb + 0];
                        if ((unsigned)(vb + 1) < 8u) a1 += sv * wr[vb + 1];
                        if ((unsigned)(vb + 2) < 8u) a2 += sv * wr[vb + 2];
                        if ((unsigned)(vb + 3) < 8u) a3 += sv * wr[vb + 3];
                    }
                }
            }
        }
        // diagonal noise: at most one of the 4 pixels has y == x
        if (y >= x0 && y < x0 + 4) {
            uint32_t e = (uint32_t)b * 784u + (uint32_t)y * 29u;
            float nz = (1.0f / alpha_p[0]) * normalf(tf_bits(kn0, kn1, e));
            int q = y - x0;
            if (q == 0) a0 += nz; else if (q == 1) a1 += nz;
            else if (q == 2) a2 += nz; else a3 += nz;
        }
        float4 res = make_float4(a0, a1, a2, a3);
        *(float4*)&out[OUT_XREC + (size_t)b * 784 + (size_t)y * 28 + x0] = res;
    }
}

// ---------------- launch ----------------
extern "C" void kernel_launch(void* const* d_in, const int* in_sizes, int n_in,
                              void* d_out, int out_size) {
    (void)in_sizes; (void)n_in; (void)out_size;
    const float* x      = (const float*)d_in[0];
    const float* enc1_w = (const float*)d_in[1];
    const float* pw1    = (const float*)d_in[2];
    const float* pw2    = (const float*)d_in[3];
    const float* enc2_w = (const float*)d_in[4];
    const float* h_w    = (const float*)d_in[5];
    const float* h_b    = (const float*)d_in[6];
    const float* mean_w = (const float*)d_in[7];
    const float* mean_b = (const float*)d_in[8];
    const float* lv_w   = (const float*)d_in[9];
    const float* lv_b   = (const float*)d_in[10];
    const float* dec2_w = (const float*)d_in[11];
    const float* dec1_w = (const float*)d_in[12];
    const float* alpha  = (const float*)d_in[13];
    float* out = (float*)d_out;

    // jax.random.key(42) = (0,42); partitionable split: key_j = tf(key, (0, j)).
    uint32_t kp0, kp1, ku0, ku1, kc0, kc1, kn0, kn1;
    tf2x32(0u, 42u, 0u, 0u, kp0, kp1);   // k_pool
    tf2x32(0u, 42u, 0u, 1u, ku0, ku1);   // k_unpool
    tf2x32(0u, 42u, 0u, 2u, kc0, kc1);   // k_code
    tf2x32(0u, 42u, 0u, 3u, kn0, kn1);   // k_noise

    k_fused<<<B_TOT, 256>>>(x, enc1_w, pw1, pw2, enc2_w, h_w, h_b,
                            mean_w, mean_b, lv_w, lv_b, dec2_w, dec1_w, alpha,
                            out, kp0, kp1, ku0, ku1, kc0, kc1, kn0, kn1);
}

// round 15
// speedup vs baseline: 1.0088x; 1.0088x over previous
#include <cuda_runtime.h>
#include <cstdint>

// ---------------- problem constants ----------------
#define B_TOT   4096
#define K1      30
#define K2      80
#define NT      7
#define NTILE   49          // 7*7
#define TPI     1470        // K1*NTILE tiles per image
#define C2N     1280        // K2*16
#define ETA_PER_B 13230     // TPI*9

// output layout: x_rec | mean | log_var | eta  (flat f32, tuple order)
#define OUT_XREC 0ull
#define OUT_MEAN 3211264ull
#define OUT_LV   8454144ull
#define OUT_ETA  13697024ull

// ---------------- inter-kernel scratch (device globals; no runtime alloc) ----
__device__ float          g_pooled[B_TOT * TPI];
__device__ unsigned short g_pyx   [B_TOT * TPI];

// ---------------- threefry2x32 (JAX-exact) ----------------
#ifdef __CUDA_ARCH__
#define TF_ROT(x, r) __funnelshift_l((x), (x), (r))
#else
#define TF_ROT(x, r) (((x) << (r)) | ((x) >> (32 - (r))))
#endif

__host__ __device__ inline void tf2x32(uint32_t k0, uint32_t k1,
                                       uint32_t x0, uint32_t x1,
                                       uint32_t& o0, uint32_t& o1) {
    uint32_t ks2 = k0 ^ k1 ^ 0x1BD11BDAu;
    x0 += k0; x1 += k1;
#define TF_RND(r) { x0 += x1; x1 = TF_ROT(x1, r); x1 ^= x0; }
    TF_RND(13) TF_RND(15) TF_RND(26) TF_RND(6)
    x0 += k1;  x1 += ks2 + 1u;
    TF_RND(17) TF_RND(29) TF_RND(16) TF_RND(24)
    x0 += ks2; x1 += k0 + 2u;
    TF_RND(13) TF_RND(15) TF_RND(26) TF_RND(6)
    x0 += k0;  x1 += k1 + 3u;
    TF_RND(17) TF_RND(29) TF_RND(16) TF_RND(24)
    x0 += k1;  x1 += ks2 + 4u;
    TF_RND(13) TF_RND(15) TF_RND(26) TF_RND(6)
    x0 += ks2; x1 += k0 + 5u;
#undef TF_RND
    o0 = x0; o1 = x1;
}

// partitionable-mode 32-bit bits: counter = 64-bit idx (hi=0), out = o0 ^ o1.
__device__ __forceinline__ uint32_t tf_bits(uint32_t k0, uint32_t k1, uint32_t idx) {
    uint32_t a, b;
    tf2x32(k0, k1, 0u, idx, a, b);
    return a ^ b;
}

__device__ __forceinline__ float bits_to_f01(uint32_t b) {
    return __uint_as_float((b >> 9) | 0x3F800000u) - 1.0f;   // [0,1)
}
// categorical score denominator: w = -log(u) > 0, u clamped away from 0 like JAX
__device__ __forceinline__ float neglogu(uint32_t b) {
    const float TINY = 1.17549435e-38f;
    float f = bits_to_f01(b);
    float u = f + TINY;
    u = fmaxf(TINY, u);
    return -__logf(u);
}
__device__ __forceinline__ float normalf(uint32_t b) {
    const float LO = -0.99999994f;   // nextafter(-1, 0)
    float f = bits_to_f01(b);
    float u = fmaf(f, 2.0f, LO);     // (hi-lo) rounds to exactly 2.0f; f*2 exact
    u = fmaxf(LO, u);
    return 1.41421356237f * erfinvf(u);
}

// ---------------- pool MLP: eta -> smem staging, UNNORMALIZED lg in regs ----
// w1p/w2p are 9x12 padded (row o at o*12, cols 9..11 zero), 16B-aligned.
// FMA order per output: tt ascending -> bit-identical to previous rounds.
__device__ __forceinline__ void pool_mlp(const float t[9],
                                         const float* __restrict__ w1p,
                                         const float* __restrict__ w2p,
                                         float* __restrict__ eta_stg,  // smem
                                         float lg[9]) {
    float h1[9];
    const float4* w1q = (const float4*)w1p;
#pragma unroll
    for (int o = 0; o < 9; o++) {
        float4 A = w1q[o * 3 + 0];
        float4 B = w1q[o * 3 + 1];
        float  c8 = w1p[o * 12 + 8];
        float a = 0.f;
        a += t[0] * A.x; a += t[1] * A.y; a += t[2] * A.z; a += t[3] * A.w;
        a += t[4] * B.x; a += t[5] * B.y; a += t[6] * B.z; a += t[7] * B.w;
        a += t[8] * c8;
        h1[o] = tanhf(a);
    }
    float mx = -3.402823466e38f;
    const float4* w2q = (const float4*)w2p;
#pragma unroll
    for (int o = 0; o < 9; o++) {
        float4 A = w2q[o * 3 + 0];
        float4 B = w2q[o * 3 + 1];
        float  c8 = w2p[o * 12 + 8];
        float a = 0.f;
        a += h1[0] * A.x; a += h1[1] * A.y; a += h1[2] * A.z; a += h1[3] * A.w;
        a += h1[4] * B.x; a += h1[5] * B.y; a += h1[6] * B.z; a += h1[7] * B.w;
        a += h1[8] * c8;
        lg[o] = a; mx = fmaxf(mx, a);
    }
    float s = 0.f;
#pragma unroll
    for (int o = 0; o < 9; o++) { lg[o] = __expf(lg[o] - mx); s += lg[o]; }
    float inv = 1.0f / s;
#pragma unroll
    for (int o = 0; o < 9; o++) eta_stg[o] = lg[o] * inv;
}

// ================= kernel 1: enc1 conv + pool MLP + eta + samplers ==========
__global__ __launch_bounds__(256) void k_stage1(
    const float* __restrict__ x,
    const float* __restrict__ enc1_w,
    const float* __restrict__ pw1, const float* __restrict__ pw2,
    float* __restrict__ out,
    uint32_t kp0, uint32_t kp1, uint32_t ku0, uint32_t ku1)
{
    __shared__ float xs[784];
    __shared__ __align__(16) float ws[K1 * 64];
    __shared__ __align__(16) float w1p[108], w2p[108];
    __shared__ __align__(16) float scratch[2304];   // eta staging

    int b = blockIdx.x, tid = threadIdx.x;

    for (int i = tid; i < 784; i += 256) xs[i] = x[(size_t)b * 784 + i];
    for (int i = tid; i < K1 * 64; i += 256) ws[i] = enc1_w[i];
    if (tid < 216) {
        int mat = tid / 108, idx = tid % 108;
        int row = idx / 12, col = idx % 12;
        float v = (col < 9) ? (mat ? pw2[row * 9 + col] : pw1[row * 9 + col]) : 0.f;
        (mat ? w2p : w1p)[idx] = v;
    }
    __syncthreads();

#pragma unroll 1
    for (int round = 0; round < 6; round++) {
        int w = round * 256 + tid;
        if (w < TPI) {
            int c = w / NTILE, nm = w % NTILE;
            int n = nm / NT, m = nm % NT;
            int y0 = 3 * n, x0 = 3 * m;
            const float* wc = &ws[c * 64];

            float t[9];
#pragma unroll
            for (int i = 0; i < 9; i++) t[i] = 0.f;

#pragma unroll
            for (int r = 0; r < 10; r++) {
                float xr[10];
#pragma unroll
                for (int v = 0; v < 10; v++) xr[v] = xs[(y0 + r) * 28 + x0 + v];
#pragma unroll
                for (int ty = 0; ty < 3; ty++) {
                    int u = r - ty;
                    if (u >= 0 && u < 8) {
                        const float4* wrow = (const float4*)&wc[u * 8];
                        float4 wa = wrow[0], wb = wrow[1];
                        float wv[8] = {wa.x, wa.y, wa.z, wa.w,
                                       wb.x, wb.y, wb.z, wb.w};
#pragma unroll
                        for (int v = 0; v < 8; v++) {
                            // per-output order: u asc, v asc (bit-identical)
                            t[ty * 3 + 0] += xr[v + 0] * wv[v];
                            t[ty * 3 + 1] += xr[v + 1] * wv[v];
                            t[ty * 3 + 2] += xr[v + 2] * wv[v];
                        }
                    }
                }
            }

            float lg[9];
            pool_mlp(t, w1p, w2p, &scratch[tid * 9], lg);

            uint32_t e0 = (uint32_t)b * (uint32_t)ETA_PER_B + (uint32_t)w * 9u;

            // argmax of lg_t / w_t via cross-multiplication (no divisions)
            float wp0 = neglogu(tf_bits(kp0, kp1, e0));
            float wu0 = neglogu(tf_bits(ku0, ku1, e0));
            float bnp = lg[0], bdp = wp0, pv = t[0];
            float bnu = lg[0], bdu = wu0;
            int z2 = 0;
#pragma unroll
            for (int tt = 1; tt < 9; tt++) {
                float wp = neglogu(tf_bits(kp0, kp1, e0 + tt));
                if (lg[tt] * bdp > bnp * wp) { bnp = lg[tt]; bdp = wp; pv = t[tt]; }
                float wu = neglogu(tf_bits(ku0, ku1, e0 + tt));
                if (lg[tt] * bdu > bnu * wu) { bnu = lg[tt]; bdu = wu; z2 = tt; }
            }
            g_pooled[(size_t)b * TPI + w] = pv;                     // coalesced
            g_pyx[(size_t)b * TPI + w] =
                (unsigned short)(((y0 + z2 / 3) << 8) | (x0 + z2 % 3));
        }
        __syncthreads();
        // coalesced eta flush for this round (float2: base is always even)
        {
            int cnt2 = ((round < 5) ? 2304 : 1710) / 2;
            size_t base = OUT_ETA + (size_t)b * ETA_PER_B + (size_t)round * 2304;
            const float2* src = (const float2*)scratch;
            float2* dst = (float2*)&out[base];
            for (int i = tid; i < cnt2; i += 256) dst[i] = src[i];
        }
        __syncthreads();
    }
}

// ================= kernel 2: conv2 + MLPs + sample + dec2 + dec1 ============
__global__ __launch_bounds__(256) void k_stage2(
    const float* __restrict__ enc2_w,
    const float* __restrict__ h_w,  const float* __restrict__ h_b,
    const float* __restrict__ mean_w, const float* __restrict__ mean_b,
    const float* __restrict__ lv_w,   const float* __restrict__ lv_b,
    const float* __restrict__ dec2_w, const float* __restrict__ dec1_w,
    const float* __restrict__ alpha_p,
    float* __restrict__ out,
    uint32_t kc0, uint32_t kc1, uint32_t kn0, uint32_t kn1)
{
    __shared__ __align__(16) float pooled[TPI];   // input, reused as s2
    __shared__ __align__(16) float ws[K1 * 64];   // dec1_w
    __shared__ __align__(16) float scratch[2560]; // flat + hsm
    __shared__ unsigned short pyx[TPI];

    float* flat = scratch;
    float* hsm  = scratch + 1280;

    int b = blockIdx.x, tid = threadIdx.x;

    for (int i = tid; i < TPI; i += 256) {
        pooled[i] = g_pooled[(size_t)b * TPI + i];
        pyx[i]    = g_pyx[(size_t)b * TPI + i];
    }
    for (int i = tid; i < K1 * 64; i += 256) ws[i] = dec1_w[i];
    __syncthreads();

    // ===== stage 2a: conv2 -> flat (thread = (k5, ij), 256 exact, 5 accs) =====
    {
        int k5 = tid / 16, ij = tid % 16;
        int ii = ij / 4, jj = ij % 4;
        float acc[5];
#pragma unroll
        for (int g = 0; g < 5; g++) acc[g] = 0.f;
        for (int c = 0; c < K1; c++) {
            float pv[16];
            const float* pc = &pooled[c * NTILE + ii * NT + jj];
#pragma unroll
            for (int u = 0; u < 4; u++)
#pragma unroll
                for (int v = 0; v < 4; v++) pv[u * 4 + v] = pc[u * NT + v];
#pragma unroll
            for (int g = 0; g < 5; g++) {
                const float4* wk4 = (const float4*)&enc2_w[((k5 * 5 + g) * K1 + c) * 16];
                float a = acc[g];
#pragma unroll
                for (int u = 0; u < 4; u++) {
                    float4 wv = wk4[u];
                    a += pv[u * 4 + 0] * wv.x;
                    a += pv[u * 4 + 1] * wv.y;
                    a += pv[u * 4 + 2] * wv.z;
                    a += pv[u * 4 + 3] * wv.w;
                }
                acc[g] = a;
            }
        }
#pragma unroll
        for (int g = 0; g < 5; g++)
            flat[(k5 * 5 + g) * 16 + ij] = acc[g];
    }
    __syncthreads();

    // ===== stage 2b: h = tanh(flat @ h_w^T + h_b) =====
    for (int r = tid; r < C2N; r += 256) {
        int k = r / 16;
        const float4* wr4 = (const float4*)&h_w[r * 16];
        const float4* fr4 = (const float4*)&flat[k * 16];
        float a = h_b[r];
#pragma unroll
        for (int q = 0; q < 4; q++) {
            float4 fv = fr4[q], wv = wr4[q];
            a += fv.x * wv.x; a += fv.y * wv.y;
            a += fv.z * wv.z; a += fv.w * wv.w;
        }
        hsm[r] = tanhf(a);
    }
    __syncthreads();

    // ===== stage 2c: mean / logvar + reparam sample (s -> flat) =====
    for (int r = tid; r < C2N; r += 256) {
        int k = r / 16;
        const float4* wm4 = (const float4*)&mean_w[r * 16];
        const float4* wl4 = (const float4*)&lv_w[r * 16];
        const float4* h4  = (const float4*)&hsm[k * 16];
        float m0 = mean_b[r], l0 = lv_b[r];
#pragma unroll
        for (int q = 0; q < 4; q++) {
            float4 hv = h4[q], wmv = wm4[q], wlv = wl4[q];
            m0 += hv.x * wmv.x; l0 += hv.x * wlv.x;
            m0 += hv.y * wmv.y; l0 += hv.y * wlv.y;
            m0 += hv.z * wmv.z; l0 += hv.z * wlv.z;
            m0 += hv.w * wmv.w; l0 += hv.w * wlv.w;
        }
        out[OUT_MEAN + (size_t)b * C2N + r] = m0;
        out[OUT_LV   + (size_t)b * C2N + r] = l0;

        uint32_t e = (uint32_t)b * (uint32_t)C2N + (uint32_t)r;
        flat[r] = m0 + __expf(0.5f * l0) * normalf(tf_bits(kc0, kc1, e));
    }
    __syncthreads();

    // ===== stage 3: dec2 transposed conv (s=flat -> s2=pooled) =====
    if (tid < K1 * NT) {                 // 210 threads: (c1, y), 7 outputs each
        int c1 = tid / NT, y = tid % NT;
        int ilo = max(0, y - 3), ihi = min(3, y);
        float acc[7];
#pragma unroll
        for (int i = 0; i < 7; i++) acc[i] = 0.f;
        for (int c2 = 0; c2 < K2; c2++) {
            const float4* s4 = (const float4*)&flat[c2 * 16];
            const float4* w4 = (const float4*)&dec2_w[(c2 * K1 + c1) * 16];
            for (int i = ilo; i <= ihi; i++) {
                float4 sv4 = s4[i];
                float4 wv4 = w4[y - i];
                float sv[4] = {sv4.x, sv4.y, sv4.z, sv4.w};
                float wv[4] = {wv4.x, wv4.y, wv4.z, wv4.w};
#pragma unroll
                for (int j = 0; j < 4; j++)
#pragma unroll
                    for (int v = 0; v < 4; v++)
                        acc[j + v] += sv[j] * wv[v];
            }
        }
#pragma unroll
        for (int xx = 0; xx < 7; xx++)
            pooled[c1 * NTILE + y * NT + xx] = acc[xx];
    }
    __syncthreads();

    // ===== stage 4: unpool + dec1 transposed conv + diag noise =====
    // thread = one row-quad of 4 consecutive pixels (28 rows x 7 quads = 196)
    if (tid < 196) {
        int y  = tid / 7;
        int x0 = (tid % 7) * 4;
        int nlo = (y  >= 9) ? (y  - 7) / 3 : 0;
        int nhi = min(6, y / 3);
        int mlo = (x0 >= 9) ? (x0 - 7) / 3 : 0;
        int mhi = min(6, (x0 + 3) / 3);
        float a0 = 0.f, a1 = 0.f, a2 = 0.f, a3 = 0.f;
        for (int c = 0; c < K1; c++) {
            int cb = c * NTILE;
            const float* wc = &ws[c * 64];
            for (int n = nlo; n <= nhi; n++) {
                int rb2 = cb + n * NT;
                for (int m = mlo; m <= mhi; m++) {
                    int idx = rb2 + m;
                    unsigned int pp = pyx[idx];
                    int uu = y - (int)(pp >> 8);
                    if ((unsigned)uu < 8u) {
                        float sv = pooled[idx];
                        const float* wr = &wc[uu * 8];
                        int vb = x0 - (int)(pp & 0xFFu);
                        if ((unsigned)(vb + 0) < 8u) a0 += sv * wr[vb + 0];
                        if ((unsigned)(vb + 1) < 8u) a1 += sv * wr[vb + 1];
                        if ((unsigned)(vb + 2) < 8u) a2 += sv * wr[vb + 2];
                        if ((unsigned)(vb + 3) < 8u) a3 += sv * wr[vb + 3];
                    }
                }
            }
        }
        // diagonal noise: at most one of the 4 pixels has y == x
        if (y >= x0 && y < x0 + 4) {
            uint32_t e = (uint32_t)b * 784u + (uint32_t)y * 29u;
            float nz = (1.0f / alpha_p[0]) * normalf(tf_bits(kn0, kn1, e));
            int q = y - x0;
            if (q == 0) a0 += nz; else if (q == 1) a1 += nz;
            else if (q == 2) a2 += nz; else a3 += nz;
        }
        float4 res = make_float4(a0, a1, a2, a3);
        *(float4*)&out[OUT_XREC + (size_t)b * 784 + (size_t)y * 28 + x0] = res;
    }
}

// ---------------- launch ----------------
extern "C" void kernel_launch(void* const* d_in, const int* in_sizes, int n_in,
                              void* d_out, int out_size) {
    (void)in_sizes; (void)n_in; (void)out_size;
    const float* x      = (const float*)d_in[0];
    const float* enc1_w = (const float*)d_in[1];
    const float* pw1    = (const float*)d_in[2];
    const float* pw2    = (const float*)d_in[3];
    const float* enc2_w = (const float*)d_in[4];
    const float* h_w    = (const float*)d_in[5];
    const float* h_b    = (const float*)d_in[6];
    const float* mean_w = (const float*)d_in[7];
    const float* mean_b = (const float*)d_in[8];
    const float* lv_w   = (const float*)d_in[9];
    const float* lv_b   = (const float*)d_in[10];
    const float* dec2_w = (const float*)d_in[11];
    const float* dec1_w = (const float*)d_in[12];
    const float* alpha  = (const float*)d_in[13];
    float* out = (float*)d_out;

    // jax.random.key(42) = (0,42); partitionable split: key_j = tf(key, (0, j)).
    uint32_t kp0, kp1, ku0, ku1, kc0, kc1, kn0, kn1;
    tf2x32(0u, 42u, 0u, 0u, kp0, kp1);   // k_pool
    tf2x32(0u, 42u, 0u, 1u, ku0, ku1);   // k_unpool
    tf2x32(0u, 42u, 0u, 2u, kc0, kc1);   // k_code
    tf2x32(0u, 42u, 0u, 3u, kn0, kn1);   // k_noise

    k_stage1<<<B_TOT, 256>>>(x, enc1_w, pw1, pw2, out, kp0, kp1, ku0, ku1);
    k_stage2<<<B_TOT, 256>>>(enc2_w, h_w, h_b, mean_w, mean_b, lv_w, lv_b,
                             dec2_w, dec1_w, alpha, out, kc0, kc1, kn0, kn1);
}

// round 16
// speedup vs baseline: 1.0894x; 1.0799x over previous
#include <cuda_runtime.h>
#include <cstdint>

// ---------------- problem constants ----------------
#define B_TOT   4096
#define K1      30
#define K2      80
#define NT      7
#define NTILE   49          // 7*7
#define TPI     1470        // K1*NTILE tiles per image
#define C2N     1280        // K2*16
#define ETA_PER_B 13230     // TPI*9

// output layout: x_rec | mean | log_var | eta  (flat f32, tuple order)
#define OUT_XREC 0ull
#define OUT_MEAN 3211264ull
#define OUT_LV   8454144ull
#define OUT_ETA  13697024ull

// ---------------- inter-kernel scratch (device globals; no runtime alloc) ----
__device__ float          g_pooled[B_TOT * TPI];
__device__ unsigned short g_pyx   [B_TOT * TPI];

// ---------------- threefry2x32 (JAX-exact) ----------------
#ifdef __CUDA_ARCH__
#define TF_ROT(x, r) __funnelshift_l((x), (x), (r))
#else
#define TF_ROT(x, r) (((x) << (r)) | ((x) >> (32 - (r))))
#endif

__host__ __device__ inline void tf2x32(uint32_t k0, uint32_t k1,
                                       uint32_t x0, uint32_t x1,
                                       uint32_t& o0, uint32_t& o1) {
    uint32_t ks2 = k0 ^ k1 ^ 0x1BD11BDAu;
    x0 += k0; x1 += k1;
#define TF_RND(r) { x0 += x1; x1 = TF_ROT(x1, r); x1 ^= x0; }
    TF_RND(13) TF_RND(15) TF_RND(26) TF_RND(6)
    x0 += k1;  x1 += ks2 + 1u;
    TF_RND(17) TF_RND(29) TF_RND(16) TF_RND(24)
    x0 += ks2; x1 += k0 + 2u;
    TF_RND(13) TF_RND(15) TF_RND(26) TF_RND(6)
    x0 += k0;  x1 += k1 + 3u;
    TF_RND(17) TF_RND(29) TF_RND(16) TF_RND(24)
    x0 += k1;  x1 += ks2 + 4u;
    TF_RND(13) TF_RND(15) TF_RND(26) TF_RND(6)
    x0 += ks2; x1 += k0 + 5u;
#undef TF_RND
    o0 = x0; o1 = x1;
}

// partitionable-mode 32-bit bits: counter = 64-bit idx (hi=0), out = o0 ^ o1.
__device__ __forceinline__ uint32_t tf_bits(uint32_t k0, uint32_t k1, uint32_t idx) {
    uint32_t a, b;
    tf2x32(k0, k1, 0u, idx, a, b);
    return a ^ b;
}

__device__ __forceinline__ float bits_to_f01(uint32_t b) {
    return __uint_as_float((b >> 9) | 0x3F800000u) - 1.0f;   // [0,1)
}
// categorical score denominator: w = -log(u) > 0, u clamped away from 0 like JAX
__device__ __forceinline__ float neglogu(uint32_t b) {
    const float TINY = 1.17549435e-38f;
    float f = bits_to_f01(b);
    float u = f + TINY;
    u = fmaxf(TINY, u);
    return -__logf(u);
}
__device__ __forceinline__ float normalf(uint32_t b) {
    const float LO = -0.99999994f;   // nextafter(-1, 0)
    float f = bits_to_f01(b);
    float u = fmaf(f, 2.0f, LO);     // (hi-lo) rounds to exactly 2.0f; f*2 exact
    u = fmaxf(LO, u);
    return 1.41421356237f * erfinvf(u);
}

// ---------------- pool MLP: eta -> smem staging, UNNORMALIZED lg in regs ----
__device__ __forceinline__ void pool_mlp(const float t[9],
                                         const float* __restrict__ w1p,
                                         const float* __restrict__ w2p,
                                         float* __restrict__ eta_stg,  // smem
                                         float lg[9]) {
    float h1[9];
    const float4* w1q = (const float4*)w1p;
#pragma unroll
    for (int o = 0; o < 9; o++) {
        float4 A = w1q[o * 3 + 0];
        float4 B = w1q[o * 3 + 1];
        float  c8 = w1p[o * 12 + 8];
        float a = 0.f;
        a += t[0] * A.x; a += t[1] * A.y; a += t[2] * A.z; a += t[3] * A.w;
        a += t[4] * B.x; a += t[5] * B.y; a += t[6] * B.z; a += t[7] * B.w;
        a += t[8] * c8;
        h1[o] = tanhf(a);
    }
    float mx = -3.402823466e38f;
    const float4* w2q = (const float4*)w2p;
#pragma unroll
    for (int o = 0; o < 9; o++) {
        float4 A = w2q[o * 3 + 0];
        float4 B = w2q[o * 3 + 1];
        float  c8 = w2p[o * 12 + 8];
        float a = 0.f;
        a += h1[0] * A.x; a += h1[1] * A.y; a += h1[2] * A.z; a += h1[3] * A.w;
        a += h1[4] * B.x; a += h1[5] * B.y; a += h1[6] * B.z; a += h1[7] * B.w;
        a += h1[8] * c8;
        lg[o] = a; mx = fmaxf(mx, a);
    }
    float s = 0.f;
#pragma unroll
    for (int o = 0; o < 9; o++) { lg[o] = __expf(lg[o] - mx); s += lg[o]; }
    float inv = 1.0f / s;
#pragma unroll
    for (int o = 0; o < 9; o++) eta_stg[o] = lg[o] * inv;
}

// ================= kernel 1: enc1 conv + pool MLP + eta + samplers ==========
__global__ __launch_bounds__(256) void k_stage1(
    const float* __restrict__ x,
    const float* __restrict__ enc1_w,
    const float* __restrict__ pw1, const float* __restrict__ pw2,
    float* __restrict__ out,
    uint32_t kp0, uint32_t kp1, uint32_t ku0, uint32_t ku1)
{
    __shared__ float xs[784];
    __shared__ __align__(16) float ws[K1 * 64];
    __shared__ __align__(16) float w1p[108], w2p[108];
    __shared__ __align__(16) float scratch[2304];   // eta staging

    int b = blockIdx.x, tid = threadIdx.x;

    for (int i = tid; i < 784; i += 256) xs[i] = x[(size_t)b * 784 + i];
    for (int i = tid; i < K1 * 64; i += 256) ws[i] = enc1_w[i];
    if (tid < 216) {
        int mat = tid / 108, idx = tid % 108;
        int row = idx / 12, col = idx % 12;
        float v = (col < 9) ? (mat ? pw2[row * 9 + col] : pw1[row * 9 + col]) : 0.f;
        (mat ? w2p : w1p)[idx] = v;
    }
    __syncthreads();

#pragma unroll 1
    for (int round = 0; round < 6; round++) {
        int w = round * 256 + tid;
        if (w < TPI) {
            int c = w / NTILE, nm = w % NTILE;
            int n = nm / NT, m = nm % NT;
            int y0 = 3 * n, x0 = 3 * m;
            const float* wc = &ws[c * 64];

            float t[9];
#pragma unroll
            for (int i = 0; i < 9; i++) t[i] = 0.f;

#pragma unroll
            for (int r = 0; r < 10; r++) {
                float xr[10];
#pragma unroll
                for (int v = 0; v < 10; v++) xr[v] = xs[(y0 + r) * 28 + x0 + v];
#pragma unroll
                for (int ty = 0; ty < 3; ty++) {
                    int u = r - ty;
                    if (u >= 0 && u < 8) {
                        const float4* wrow = (const float4*)&wc[u * 8];
                        float4 wa = wrow[0], wb = wrow[1];
                        float wv[8] = {wa.x, wa.y, wa.z, wa.w,
                                       wb.x, wb.y, wb.z, wb.w};
#pragma unroll
                        for (int v = 0; v < 8; v++) {
                            // per-output order: u asc, v asc (bit-identical)
                            t[ty * 3 + 0] += xr[v + 0] * wv[v];
                            t[ty * 3 + 1] += xr[v + 1] * wv[v];
                            t[ty * 3 + 2] += xr[v + 2] * wv[v];
                        }
                    }
                }
            }

            float lg[9];
            pool_mlp(t, w1p, w2p, &scratch[tid * 9], lg);

            uint32_t e0 = (uint32_t)b * (uint32_t)ETA_PER_B + (uint32_t)w * 9u;

            // argmax of lg_t / w_t via cross-multiplication (no divisions)
            float wp0 = neglogu(tf_bits(kp0, kp1, e0));
            float wu0 = neglogu(tf_bits(ku0, ku1, e0));
            float bnp = lg[0], bdp = wp0, pv = t[0];
            float bnu = lg[0], bdu = wu0;
            int z2 = 0;
#pragma unroll
            for (int tt = 1; tt < 9; tt++) {
                float wp = neglogu(tf_bits(kp0, kp1, e0 + tt));
                if (lg[tt] * bdp > bnp * wp) { bnp = lg[tt]; bdp = wp; pv = t[tt]; }
                float wu = neglogu(tf_bits(ku0, ku1, e0 + tt));
                if (lg[tt] * bdu > bnu * wu) { bnu = lg[tt]; bdu = wu; z2 = tt; }
            }
            g_pooled[(size_t)b * TPI + w] = pv;                     // coalesced
            g_pyx[(size_t)b * TPI + w] =
                (unsigned short)(((y0 + z2 / 3) << 8) | (x0 + z2 % 3));
        }
        __syncthreads();
        // coalesced eta flush for this round (float2: base is always even)
        {
            int cnt2 = ((round < 5) ? 2304 : 1710) / 2;
            size_t base = OUT_ETA + (size_t)b * ETA_PER_B + (size_t)round * 2304;
            const float2* src = (const float2*)scratch;
            float2* dst = (float2*)&out[base];
            for (int i = tid; i < cnt2; i += 256) dst[i] = src[i];
        }
        __syncthreads();
    }
}

// ============ kernel 2: TWO images per block; weights loaded once ===========
__global__ __launch_bounds__(256) void k_stage2(
    const float* __restrict__ enc2_w,
    const float* __restrict__ h_w,  const float* __restrict__ h_b,
    const float* __restrict__ mean_w, const float* __restrict__ mean_b,
    const float* __restrict__ lv_w,   const float* __restrict__ lv_b,
    const float* __restrict__ dec2_w, const float* __restrict__ dec1_w,
    const float* __restrict__ alpha_p,
    float* __restrict__ out,
    uint32_t kc0, uint32_t kc1, uint32_t kn0, uint32_t kn1)
{
    __shared__ __align__(16) float pooled[2 * TPI];   // input, reused as s2
    __shared__ __align__(16) float ws[K1 * 64];       // dec1_w
    __shared__ __align__(16) float flat[2 * C2N];     // conv2 out, reused as s
    __shared__ __align__(16) float hsm[2 * C2N];
    __shared__ unsigned short pyx[2 * TPI];

    int tid = threadIdx.x;
    int b0 = 2 * blockIdx.x, b1 = b0 + 1;

    for (int i = tid; i < TPI; i += 256) {
        pooled[i]       = g_pooled[(size_t)b0 * TPI + i];
        pooled[TPI + i] = g_pooled[(size_t)b1 * TPI + i];
        pyx[i]          = g_pyx[(size_t)b0 * TPI + i];
        pyx[TPI + i]    = g_pyx[(size_t)b1 * TPI + i];
    }
    for (int i = tid; i < K1 * 64; i += 256) ws[i] = dec1_w[i];
    __syncthreads();

    // ===== stage 2a: conv2 -> flat; weights shared across both images =====
    {
        int k5 = tid / 16, ij = tid % 16;
        int ii = ij / 4, jj = ij % 4;
        float acc0[5], acc1[5];
#pragma unroll
        for (int g = 0; g < 5; g++) { acc0[g] = 0.f; acc1[g] = 0.f; }
        for (int c = 0; c < K1; c++) {
            float pv0[16], pv1[16];
            const float* pc0 = &pooled[c * NTILE + ii * NT + jj];
            const float* pc1 = &pooled[TPI + c * NTILE + ii * NT + jj];
#pragma unroll
            for (int u = 0; u < 4; u++)
#pragma unroll
                for (int v = 0; v < 4; v++) {
                    pv0[u * 4 + v] = pc0[u * NT + v];
                    pv1[u * 4 + v] = pc1[u * NT + v];
                }
#pragma unroll
            for (int g = 0; g < 5; g++) {
                const float4* wk4 = (const float4*)&enc2_w[((k5 * 5 + g) * K1 + c) * 16];
                float a0 = acc0[g], a1 = acc1[g];
#pragma unroll
                for (int u = 0; u < 4; u++) {
                    float4 wv = wk4[u];
                    a0 += pv0[u * 4 + 0] * wv.x;
                    a0 += pv0[u * 4 + 1] * wv.y;
                    a0 += pv0[u * 4 + 2] * wv.z;
                    a0 += pv0[u * 4 + 3] * wv.w;
                    a1 += pv1[u * 4 + 0] * wv.x;
                    a1 += pv1[u * 4 + 1] * wv.y;
                    a1 += pv1[u * 4 + 2] * wv.z;
                    a1 += pv1[u * 4 + 3] * wv.w;
                }
                acc0[g] = a0; acc1[g] = a1;
            }
        }
#pragma unroll
        for (int g = 0; g < 5; g++) {
            flat[(k5 * 5 + g) * 16 + ij]       = acc0[g];
            flat[C2N + (k5 * 5 + g) * 16 + ij] = acc1[g];
        }
    }
    __syncthreads();

    // ===== stage 2b: h = tanh(flat @ h_w^T + h_b); weights shared =====
    for (int r = tid; r < C2N; r += 256) {
        int k = r / 16;
        const float4* wr4 = (const float4*)&h_w[r * 16];
        const float4* f0 = (const float4*)&flat[k * 16];
        const float4* f1 = (const float4*)&flat[C2N + k * 16];
        float a0 = h_b[r], a1 = a0;
#pragma unroll
        for (int q = 0; q < 4; q++) {
            float4 wv = wr4[q];
            float4 v0 = f0[q], v1 = f1[q];
            a0 += v0.x * wv.x; a0 += v0.y * wv.y; a0 += v0.z * wv.z; a0 += v0.w * wv.w;
            a1 += v1.x * wv.x; a1 += v1.y * wv.y; a1 += v1.z * wv.z; a1 += v1.w * wv.w;
        }
        hsm[r]       = tanhf(a0);
        hsm[C2N + r] = tanhf(a1);
    }
    __syncthreads();

    // ===== stage 2c: mean / logvar + reparam sample; weights shared =====
    for (int r = tid; r < C2N; r += 256) {
        int k = r / 16;
        const float4* wm4 = (const float4*)&mean_w[r * 16];
        const float4* wl4 = (const float4*)&lv_w[r * 16];
        const float4* h0  = (const float4*)&hsm[k * 16];
        const float4* h1  = (const float4*)&hsm[C2N + k * 16];
        float mb = mean_b[r], lb = lv_b[r];
        float m0 = mb, l0 = lb, m1 = mb, l1 = lb;
#pragma unroll
        for (int q = 0; q < 4; q++) {
            float4 wmv = wm4[q], wlv = wl4[q];
            float4 v0 = h0[q], v1 = h1[q];
            m0 += v0.x * wmv.x; l0 += v0.x * wlv.x;
            m0 += v0.y * wmv.y; l0 += v0.y * wlv.y;
            m0 += v0.z * wmv.z; l0 += v0.z * wlv.z;
            m0 += v0.w * wmv.w; l0 += v0.w * wlv.w;
            m1 += v1.x * wmv.x; l1 += v1.x * wlv.x;
            m1 += v1.y * wmv.y; l1 += v1.y * wlv.y;
            m1 += v1.z * wmv.z; l1 += v1.z * wlv.z;
            m1 += v1.w * wmv.w; l1 += v1.w * wlv.w;
        }
        out[OUT_MEAN + (size_t)b0 * C2N + r] = m0;
        out[OUT_LV   + (size_t)b0 * C2N + r] = l0;
        out[OUT_MEAN + (size_t)b1 * C2N + r] = m1;
        out[OUT_LV   + (size_t)b1 * C2N + r] = l1;

        uint32_t e0 = (uint32_t)b0 * (uint32_t)C2N + (uint32_t)r;
        uint32_t e1 = (uint32_t)b1 * (uint32_t)C2N + (uint32_t)r;
        flat[r]       = m0 + __expf(0.5f * l0) * normalf(tf_bits(kc0, kc1, e0));
        flat[C2N + r] = m1 + __expf(0.5f * l1) * normalf(tf_bits(kc0, kc1, e1));
    }
    __syncthreads();

    // ===== stage 3: dec2 transposed conv; weights shared across images =====
    if (tid < K1 * NT) {                 // 210 threads: (c1, y), 7 outputs x2
        int c1 = tid / NT, y = tid % NT;
        int ilo = max(0, y - 3), ihi = min(3, y);
        float acc0[7], acc1[7];
#pragma unroll
        for (int i = 0; i < 7; i++) { acc0[i] = 0.f; acc1[i] = 0.f; }
        for (int c2 = 0; c2 < K2; c2++) {
            const float4* s40 = (const float4*)&flat[c2 * 16];
            const float4* s41 = (const float4*)&flat[C2N + c2 * 16];
            const float4* w4  = (const float4*)&dec2_w[(c2 * K1 + c1) * 16];
            for (int i = ilo; i <= ihi; i++) {
                float4 wv4 = w4[y - i];
                float wv[4] = {wv4.x, wv4.y, wv4.z, wv4.w};
                float4 sv40 = s40[i];
                float sv0[4] = {sv40.x, sv40.y, sv40.z, sv40.w};
#pragma unroll
                for (int j = 0; j < 4; j++)
#pragma unroll
                    for (int v = 0; v < 4; v++)
                        acc0[j + v] += sv0[j] * wv[v];
                float4 sv41 = s41[i];
                float sv1[4] = {sv41.x, sv41.y, sv41.z, sv41.w};
#pragma unroll
                for (int j = 0; j < 4; j++)
#pragma unroll
                    for (int v = 0; v < 4; v++)
                        acc1[j + v] += sv1[j] * wv[v];
            }
        }
#pragma unroll
        for (int xx = 0; xx < 7; xx++) {
            pooled[c1 * NTILE + y * NT + xx]       = acc0[xx];
            pooled[TPI + c1 * NTILE + y * NT + xx] = acc1[xx];
        }
    }
    __syncthreads();

    // ===== stage 4: unpool + dec1 transposed conv + diag noise (2 images) =====
    // work item = one row-quad of 4 pixels; 196 per image, 392 total
#pragma unroll 1
    for (int q = tid; q < 392; q += 256) {
        int img = (q >= 196);
        int pq  = img ? (q - 196) : q;
        int bb  = img ? b1 : b0;
        const float* pimg = &pooled[img * TPI];
        const unsigned short* pyi = &pyx[img * TPI];
        int y  = pq / 7;
        int x0 = (pq % 7) * 4;
        int nlo = (y  >= 9) ? (y  - 7) / 3 : 0;
        int nhi = min(6, y / 3);
        int mlo = (x0 >= 9) ? (x0 - 7) / 3 : 0;
        int mhi = min(6, (x0 + 3) / 3);
        float a0 = 0.f, a1 = 0.f, a2 = 0.f, a3 = 0.f;
        for (int c = 0; c < K1; c++) {
            int cb = c * NTILE;
            const float* wc = &ws[c * 64];
            for (int n = nlo; n <= nhi; n++) {
                int rb2 = cb + n * NT;
                for (int m = mlo; m <= mhi; m++) {
                    int idx = rb2 + m;
                    unsigned int pp = pyi[idx];
                    int uu = y - (int)(pp >> 8);
                    if ((unsigned)uu < 8u) {
                        float sv = pimg[idx];
                        const float* wr = &wc[uu * 8];
                        int vb = x0 - (int)(pp & 0xFFu);
                        if ((unsigned)(vb + 0) < 8u) a0 += sv * wr[vb + 0];
                        if ((unsigned)(vb + 1) < 8u) a1 += sv * wr[vb + 1];
                        if ((unsigned)(vb + 2) < 8u) a2 += sv * wr[vb + 2];
                        if ((unsigned)(vb + 3) < 8u) a3 += sv * wr[vb + 3];
                    }
                }
            }
        }
        // diagonal noise: at most one of the 4 pixels has y == x
        if (y >= x0 && y < x0 + 4) {
            uint32_t e = (uint32_t)bb * 784u + (uint32_t)y * 29u;
            float nz = (1.0f / alpha_p[0]) * normalf(tf_bits(kn0, kn1, e));
            int qq = y - x0;
            if (qq == 0) a0 += nz; else if (qq == 1) a1 += nz;
            else if (qq == 2) a2 += nz; else a3 += nz;
        }
        float4 res = make_float4(a0, a1, a2, a3);
        *(float4*)&out[OUT_XREC + (size_t)bb * 784 + (size_t)y * 28 + x0] = res;
    }
}

// ---------------- launch ----------------
extern "C" void kernel_launch(void* const* d_in, const int* in_sizes, int n_in,
                              void* d_out, int out_size) {
    (void)in_sizes; (void)n_in; (void)out_size;
    const float* x      = (const float*)d_in[0];
    const float* enc1_w = (const float*)d_in[1];
    const float* pw1    = (const float*)d_in[2];
    const float* pw2    = (const float*)d_in[3];
    const float* enc2_w = (const float*)d_in[4];
    const float* h_w    = (const float*)d_in[5];
    const float* h_b    = (const float*)d_in[6];
    const float* mean_w = (const float*)d_in[7];
    const float* mean_b = (const float*)d_in[8];
    const float* lv_w   = (const float*)d_in[9];
    const float* lv_b   = (const float*)d_in[10];
    const float* dec2_w = (const float*)d_in[11];
    const float* dec1_w = (const float*)d_in[12];
    const float* alpha  = (const float*)d_in[13];
    float* out = (float*)d_out;

    // jax.random.key(42) = (0,42); partitionable split: key_j = tf(key, (0, j)).
    uint32_t kp0, kp1, ku0, ku1, kc0, kc1, kn0, kn1;
    tf2x32(0u, 42u, 0u, 0u, kp0, kp1);   // k_pool
    tf2x32(0u, 42u, 0u, 1u, ku0, ku1);   // k_unpool
    tf2x32(0u, 42u, 0u, 2u, kc0, kc1);   // k_code
    tf2x32(0u, 42u, 0u, 3u, kn0, kn1);   // k_noise

    k_stage1<<<B_TOT, 256>>>(x, enc1_w, pw1, pw2, out, kp0, kp1, ku0, ku1);
    k_stage2<<<B_TOT / 2, 256>>>(enc2_w, h_w, h_b, mean_w, mean_b, lv_w, lv_b,
                                 dec2_w, dec1_w, alpha, out, kc0, kc1, kn0, kn1);
}

// round 17
// speedup vs baseline: 1.0913x; 1.0017x over previous
#include <cuda_runtime.h>
#include <cstdint>

// ---------------- problem constants ----------------
#define B_TOT   4096
#define K1      30
#define K2      80
#define NT      7
#define NTILE   49          // 7*7
#define TPI     1470        // K1*NTILE tiles per image
#define C2N     1280        // K2*16
#define ETA_PER_B 13230     // TPI*9

// output layout: x_rec | mean | log_var | eta  (flat f32, tuple order)
#define OUT_XREC 0ull
#define OUT_MEAN 3211264ull
#define OUT_LV   8454144ull
#define OUT_ETA  13697024ull

// ---------------- inter-kernel scratch (device globals; no runtime alloc) ----
__device__ float         g_pooled[B_TOT * TPI];
__device__ unsigned char g_zs    [B_TOT * TPI];   // packed (zy<<2)|zx per tile

// ---------------- threefry2x32 (JAX-exact) ----------------
#ifdef __CUDA_ARCH__
#define TF_ROT(x, r) __funnelshift_l((x), (x), (r))
#else
#define TF_ROT(x, r) (((x) << (r)) | ((x) >> (32 - (r))))
#endif

__host__ __device__ inline void tf2x32(uint32_t k0, uint32_t k1,
                                       uint32_t x0, uint32_t x1,
                                       uint32_t& o0, uint32_t& o1) {
    uint32_t ks2 = k0 ^ k1 ^ 0x1BD11BDAu;
    x0 += k0; x1 += k1;
#define TF_RND(r) { x0 += x1; x1 = TF_ROT(x1, r); x1 ^= x0; }
    TF_RND(13) TF_RND(15) TF_RND(26) TF_RND(6)
    x0 += k1;  x1 += ks2 + 1u;
    TF_RND(17) TF_RND(29) TF_RND(16) TF_RND(24)
    x0 += ks2; x1 += k0 + 2u;
    TF_RND(13) TF_RND(15) TF_RND(26) TF_RND(6)
    x0 += k0;  x1 += k1 + 3u;
    TF_RND(17) TF_RND(29) TF_RND(16) TF_RND(24)
    x0 += k1;  x1 += ks2 + 4u;
    TF_RND(13) TF_RND(15) TF_RND(26) TF_RND(6)
    x0 += ks2; x1 += k0 + 5u;
#undef TF_RND
    o0 = x0; o1 = x1;
}

// partitionable-mode 32-bit bits: counter = 64-bit idx (hi=0), out = o0 ^ o1.
__device__ __forceinline__ uint32_t tf_bits(uint32_t k0, uint32_t k1, uint32_t idx) {
    uint32_t a, b;
    tf2x32(k0, k1, 0u, idx, a, b);
    return a ^ b;
}

__device__ __forceinline__ float bits_to_f01(uint32_t b) {
    return __uint_as_float((b >> 9) | 0x3F800000u) - 1.0f;   // [0,1)
}
// categorical score denominator: w = -log(u) > 0, u clamped away from 0 like JAX
__device__ __forceinline__ float neglogu(uint32_t b) {
    const float TINY = 1.17549435e-38f;
    float f = bits_to_f01(b);
    float u = f + TINY;
    u = fmaxf(TINY, u);
    return -__logf(u);
}
__device__ __forceinline__ float normalf(uint32_t b) {
    const float LO = -0.99999994f;   // nextafter(-1, 0)
    float f = bits_to_f01(b);
    float u = fmaf(f, 2.0f, LO);     // (hi-lo) rounds to exactly 2.0f; f*2 exact
    u = fmaxf(LO, u);
    return 1.41421356237f * erfinvf(u);
}

// ---------------- pool MLP: eta -> smem staging, UNNORMALIZED lg in regs ----
__device__ __forceinline__ void pool_mlp(const float t[9],
                                         const float* __restrict__ w1p,
                                         const float* __restrict__ w2p,
                                         float* __restrict__ eta_stg,  // smem
                                         float lg[9]) {
    float h1[9];
    const float4* w1q = (const float4*)w1p;
#pragma unroll
    for (int o = 0; o < 9; o++) {
        float4 A = w1q[o * 3 + 0];
        float4 B = w1q[o * 3 + 1];
        float  c8 = w1p[o * 12 + 8];
        float a = 0.f;
        a += t[0] * A.x; a += t[1] * A.y; a += t[2] * A.z; a += t[3] * A.w;
        a += t[4] * B.x; a += t[5] * B.y; a += t[6] * B.z; a += t[7] * B.w;
        a += t[8] * c8;
        h1[o] = tanhf(a);
    }
    float mx = -3.402823466e38f;
    const float4* w2q = (const float4*)w2p;
#pragma unroll
    for (int o = 0; o < 9; o++) {
        float4 A = w2q[o * 3 + 0];
        float4 B = w2q[o * 3 + 1];
        float  c8 = w2p[o * 12 + 8];
        float a = 0.f;
        a += h1[0] * A.x; a += h1[1] * A.y; a += h1[2] * A.z; a += h1[3] * A.w;
        a += h1[4] * B.x; a += h1[5] * B.y; a += h1[6] * B.z; a += h1[7] * B.w;
        a += h1[8] * c8;
        lg[o] = a; mx = fmaxf(mx, a);
    }
    float s = 0.f;
#pragma unroll
    for (int o = 0; o < 9; o++) { lg[o] = __expf(lg[o] - mx); s += lg[o]; }
    float inv = 1.0f / s;
#pragma unroll
    for (int o = 0; o < 9; o++) eta_stg[o] = lg[o] * inv;
}

// ================= kernel 1: enc1 conv + pool MLP + eta + samplers ==========
__global__ __launch_bounds__(256) void k_stage1(
    const float* __restrict__ x,
    const float* __restrict__ enc1_w,
    const float* __restrict__ pw1, const float* __restrict__ pw2,
    float* __restrict__ out,
    uint32_t kp0, uint32_t kp1, uint32_t ku0, uint32_t ku1)
{
    __shared__ float xs[784];
    __shared__ __align__(16) float ws[K1 * 64];
    __shared__ __align__(16) float w1p[108], w2p[108];
    __shared__ __align__(16) float scratch[2304];   // eta staging

    int b = blockIdx.x, tid = threadIdx.x;

    for (int i = tid; i < 784; i += 256) xs[i] = x[(size_t)b * 784 + i];
    for (int i = tid; i < K1 * 64; i += 256) ws[i] = enc1_w[i];
    if (tid < 216) {
        int mat = tid / 108, idx = tid % 108;
        int row = idx / 12, col = idx % 12;
        float v = (col < 9) ? (mat ? pw2[row * 9 + col] : pw1[row * 9 + col]) : 0.f;
        (mat ? w2p : w1p)[idx] = v;
    }
    __syncthreads();

#pragma unroll 1
    for (int round = 0; round < 6; round++) {
        int w = round * 256 + tid;
        if (w < TPI) {
            int c = w / NTILE, nm = w % NTILE;
            int n = nm / NT, m = nm % NT;
            int y0 = 3 * n, x0 = 3 * m;
            const float* wc = &ws[c * 64];

            float t[9];
#pragma unroll
            for (int i = 0; i < 9; i++) t[i] = 0.f;

#pragma unroll
            for (int r = 0; r < 10; r++) {
                float xr[10];
#pragma unroll
                for (int v = 0; v < 10; v++) xr[v] = xs[(y0 + r) * 28 + x0 + v];
#pragma unroll
                for (int ty = 0; ty < 3; ty++) {
                    int u = r - ty;
                    if (u >= 0 && u < 8) {
                        const float4* wrow = (const float4*)&wc[u * 8];
                        float4 wa = wrow[0], wb = wrow[1];
                        float wv[8] = {wa.x, wa.y, wa.z, wa.w,
                                       wb.x, wb.y, wb.z, wb.w};
#pragma unroll
                        for (int v = 0; v < 8; v++) {
                            // per-output order: u asc, v asc (bit-identical)
                            t[ty * 3 + 0] += xr[v + 0] * wv[v];
                            t[ty * 3 + 1] += xr[v + 1] * wv[v];
                            t[ty * 3 + 2] += xr[v + 2] * wv[v];
                        }
                    }
                }
            }

            float lg[9];
            pool_mlp(t, w1p, w2p, &scratch[tid * 9], lg);

            uint32_t e0 = (uint32_t)b * (uint32_t)ETA_PER_B + (uint32_t)w * 9u;

            // argmax of lg_t / w_t via cross-multiplication (no divisions)
            float wp0 = neglogu(tf_bits(kp0, kp1, e0));
            float wu0 = neglogu(tf_bits(ku0, ku1, e0));
            float bnp = lg[0], bdp = wp0, pv = t[0];
            float bnu = lg[0], bdu = wu0;
            int z2 = 0;
#pragma unroll
            for (int tt = 1; tt < 9; tt++) {
                float wp = neglogu(tf_bits(kp0, kp1, e0 + tt));
                if (lg[tt] * bdp > bnp * wp) { bnp = lg[tt]; bdp = wp; pv = t[tt]; }
                float wu = neglogu(tf_bits(ku0, ku1, e0 + tt));
                if (lg[tt] * bdu > bnu * wu) { bnu = lg[tt]; bdu = wu; z2 = tt; }
            }
            g_pooled[(size_t)b * TPI + w] = pv;                     // coalesced
            int zy = z2 / 3, zx = z2 - 3 * zy;
            g_zs[(size_t)b * TPI + w] = (unsigned char)((zy << 2) | zx);
        }
        __syncthreads();
        // coalesced eta flush for this round (float2: base is always even)
        {
            int cnt2 = ((round < 5) ? 2304 : 1710) / 2;
            size_t base = OUT_ETA + (size_t)b * ETA_PER_B + (size_t)round * 2304;
            const float2* src = (const float2*)scratch;
            float2* dst = (float2*)&out[base];
            for (int i = tid; i < cnt2; i += 256) dst[i] = src[i];
        }
        __syncthreads();
    }
}

// ============ kernel 2: TWO images per block; slim smem for occupancy =======
__global__ __launch_bounds__(256) void k_stage2(
    const float* __restrict__ enc2_w,
    const float* __restrict__ h_w,  const float* __restrict__ h_b,
    const float* __restrict__ mean_w, const float* __restrict__ mean_b,
    const float* __restrict__ lv_w,   const float* __restrict__ lv_b,
    const float* __restrict__ dec2_w, const float* __restrict__ dec1_w,
    const float* __restrict__ alpha_p,
    float* __restrict__ out,
    uint32_t kc0, uint32_t kc1, uint32_t kn0, uint32_t kn1)
{
    // pooled: raw input for 2a, then ALIASED as hsm (2b->2c), then s2 (stage 3+)
    __shared__ __align__(16) float pooled[2 * TPI];
    __shared__ __align__(16) float flat[2 * C2N];     // conv2 out, reused as s
    __shared__ __align__(16) float ws[K1 * 64];       // dec1_w
    __shared__ unsigned char zs[2 * TPI];

    float* hsm = pooled;   // alias: raw pooled dead after 2a; s2 written after 2c

    int tid = threadIdx.x;
    int b0 = 2 * blockIdx.x, b1 = b0 + 1;

    for (int i = tid; i < TPI; i += 256) {
        pooled[i]       = g_pooled[(size_t)b0 * TPI + i];
        pooled[TPI + i] = g_pooled[(size_t)b1 * TPI + i];
        zs[i]           = g_zs[(size_t)b0 * TPI + i];
        zs[TPI + i]     = g_zs[(size_t)b1 * TPI + i];
    }
    for (int i = tid; i < K1 * 64; i += 256) ws[i] = dec1_w[i];
    __syncthreads();

    // ===== stage 2a: conv2 -> flat; weights shared across both images =====
    {
        int k5 = tid / 16, ij = tid % 16;
        int ii = ij / 4, jj = ij % 4;
        float acc0[5], acc1[5];
#pragma unroll
        for (int g = 0; g < 5; g++) { acc0[g] = 0.f; acc1[g] = 0.f; }
        for (int c = 0; c < K1; c++) {
            float pv0[16], pv1[16];
            const float* pc0 = &pooled[c * NTILE + ii * NT + jj];
            const float* pc1 = &pooled[TPI + c * NTILE + ii * NT + jj];
#pragma unroll
            for (int u = 0; u < 4; u++)
#pragma unroll
                for (int v = 0; v < 4; v++) {
                    pv0[u * 4 + v] = pc0[u * NT + v];
                    pv1[u * 4 + v] = pc1[u * NT + v];
                }
#pragma unroll
            for (int g = 0; g < 5; g++) {
                const float4* wk4 = (const float4*)&enc2_w[((k5 * 5 + g) * K1 + c) * 16];
                float a0 = acc0[g], a1 = acc1[g];
#pragma unroll
                for (int u = 0; u < 4; u++) {
                    float4 wv = wk4[u];
                    a0 += pv0[u * 4 + 0] * wv.x;
                    a0 += pv0[u * 4 + 1] * wv.y;
                    a0 += pv0[u * 4 + 2] * wv.z;
                    a0 += pv0[u * 4 + 3] * wv.w;
                    a1 += pv1[u * 4 + 0] * wv.x;
                    a1 += pv1[u * 4 + 1] * wv.y;
                    a1 += pv1[u * 4 + 2] * wv.z;
                    a1 += pv1[u * 4 + 3] * wv.w;
                }
                acc0[g] = a0; acc1[g] = a1;
            }
        }
#pragma unroll
        for (int g = 0; g < 5; g++) {
            flat[(k5 * 5 + g) * 16 + ij]       = acc0[g];
            flat[C2N + (k5 * 5 + g) * 16 + ij] = acc1[g];
        }
    }
    __syncthreads();

    // ===== stage 2b: h = tanh(flat @ h_w^T + h_b); h -> hsm (pooled alias) =====
    for (int r = tid; r < C2N; r += 256) {
        int k = r / 16;
        const float4* wr4 = (const float4*)&h_w[r * 16];
        const float4* f0 = (const float4*)&flat[k * 16];
        const float4* f1 = (const float4*)&flat[C2N + k * 16];
        float a0 = h_b[r], a1 = a0;
#pragma unroll
        for (int q = 0; q < 4; q++) {
            float4 wv = wr4[q];
            float4 v0 = f0[q], v1 = f1[q];
            a0 += v0.x * wv.x; a0 += v0.y * wv.y; a0 += v0.z * wv.z; a0 += v0.w * wv.w;
            a1 += v1.x * wv.x; a1 += v1.y * wv.y; a1 += v1.z * wv.z; a1 += v1.w * wv.w;
        }
        hsm[r]       = tanhf(a0);
        hsm[C2N + r] = tanhf(a1);
    }
    __syncthreads();

    // ===== stage 2c: mean / logvar + reparam sample; weights shared =====
    for (int r = tid; r < C2N; r += 256) {
        int k = r / 16;
        const float4* wm4 = (const float4*)&mean_w[r * 16];
        const float4* wl4 = (const float4*)&lv_w[r * 16];
        const float4* h0  = (const float4*)&hsm[k * 16];
        const float4* h1  = (const float4*)&hsm[C2N + k * 16];
        float mb = mean_b[r], lb = lv_b[r];
        float m0 = mb, l0 = lb, m1 = mb, l1 = lb;
#pragma unroll
        for (int q = 0; q < 4; q++) {
            float4 wmv = wm4[q], wlv = wl4[q];
            float4 v0 = h0[q], v1 = h1[q];
            m0 += v0.x * wmv.x; l0 += v0.x * wlv.x;
            m0 += v0.y * wmv.y; l0 += v0.y * wlv.y;
            m0 += v0.z * wmv.z; l0 += v0.z * wlv.z;
            m0 += v0.w * wmv.w; l0 += v0.w * wlv.w;
            m1 += v1.x * wmv.x; l1 += v1.x * wlv.x;
            m1 += v1.y * wmv.y; l1 += v1.y * wlv.y;
            m1 += v1.z * wmv.z; l1 += v1.z * wlv.z;
            m1 += v1.w * wmv.w; l1 += v1.w * wlv.w;
        }
        out[OUT_MEAN + (size_t)b0 * C2N + r] = m0;
        out[OUT_LV   + (size_t)b0 * C2N + r] = l0;
        out[OUT_MEAN + (size_t)b1 * C2N + r] = m1;
        out[OUT_LV   + (size_t)b1 * C2N + r] = l1;

        uint32_t e0 = (uint32_t)b0 * (uint32_t)C2N + (uint32_t)r;
        uint32_t e1 = (uint32_t)b1 * (uint32_t)C2N + (uint32_t)r;
        flat[r]       = m0 + __expf(0.5f * l0) * normalf(tf_bits(kc0, kc1, e0));
        flat[C2N + r] = m1 + __expf(0.5f * l1) * normalf(tf_bits(kc0, kc1, e1));
    }
    __syncthreads();

    // ===== stage 3: dec2 transposed conv (s=flat -> s2=pooled) =====
    if (tid < K1 * NT) {                 // 210 threads: (c1, y), 7 outputs x2
        int c1 = tid / NT, y = tid % NT;
        int ilo = max(0, y - 3), ihi = min(3, y);
        float acc0[7], acc1[7];
#pragma unroll
        for (int i = 0; i < 7; i++) { acc0[i] = 0.f; acc1[i] = 0.f; }
        for (int c2 = 0; c2 < K2; c2++) {
            const float4* s40 = (const float4*)&flat[c2 * 16];
            const float4* s41 = (const float4*)&flat[C2N + c2 * 16];
            const float4* w4  = (const float4*)&dec2_w[(c2 * K1 + c1) * 16];
            for (int i = ilo; i <= ihi; i++) {
                float4 wv4 = w4[y - i];
                float wv[4] = {wv4.x, wv4.y, wv4.z, wv4.w};
                float4 sv40 = s40[i];
                float sv0[4] = {sv40.x, sv40.y, sv40.z, sv40.w};
#pragma unroll
                for (int j = 0; j < 4; j++)
#pragma unroll
                    for (int v = 0; v < 4; v++)
                        acc0[j + v] += sv0[j] * wv[v];
                float4 sv41 = s41[i];
                float sv1[4] = {sv41.x, sv41.y, sv41.z, sv41.w};
#pragma unroll
                for (int j = 0; j < 4; j++)
#pragma unroll
                    for (int v = 0; v < 4; v++)
                        acc1[j + v] += sv1[j] * wv[v];
            }
        }
#pragma unroll
        for (int xx = 0; xx < 7; xx++) {
            pooled[c1 * NTILE + y * NT + xx]       = acc0[xx];
            pooled[TPI + c1 * NTILE + y * NT + xx] = acc1[xx];
        }
    }
    __syncthreads();

    // ===== stage 4: unpool + dec1 transposed conv + diag noise (2 images) =====
    // work item = one row-quad of 4 pixels; 196 per image, 392 total
#pragma unroll 1
    for (int q = tid; q < 392; q += 256) {
        int img = (q >= 196);
        int pq  = img ? (q - 196) : q;
        int bb  = img ? b1 : b0;
        const float* pimg = &pooled[img * TPI];
        const unsigned char* zsi = &zs[img * TPI];
        int y  = pq / 7;
        int x0 = (pq % 7) * 4;
        int nlo = (y  >= 9) ? (y  - 7) / 3 : 0;
        int nhi = min(6, y / 3);
        int mlo = (x0 >= 9) ? (x0 - 7) / 3 : 0;
        int mhi = min(6, (x0 + 3) / 3);
        float a0 = 0.f, a1 = 0.f, a2 = 0.f, a3 = 0.f;
        for (int c = 0; c < K1; c++) {
            int cb = c * NTILE;
            const float* wc = &ws[c * 64];
            for (int n = nlo; n <= nhi; n++) {
                int rb2 = cb + n * NT;
                int un  = y - 3 * n;
                for (int m = mlo; m <= mhi; m++) {
                    int idx = rb2 + m;
                    int zv = (int)zsi[idx];
                    int uu = un - (zv >> 2);
                    if ((unsigned)uu < 8u) {
                        float sv = pimg[idx];
                        const float* wr = &wc[uu * 8];
                        int vb = x0 - 3 * m - (zv & 3);
                        if ((unsigned)(vb + 0) < 8u) a0 += sv * wr[vb + 0];
                        if ((unsigned)(vb + 1) < 8u) a1 += sv * wr[vb + 1];
                        if ((unsigned)(vb + 2) < 8u) a2 += sv * wr[vb + 2];
                        if ((unsigned)(vb + 3) < 8u) a3 += sv * wr[vb + 3];
                    }
                }
            }
        }
        // diagonal noise: at most one of the 4 pixels has y == x
        if (y >= x0 && y < x0 + 4) {
            uint32_t e = (uint32_t)bb * 784u + (uint32_t)y * 29u;
            float nz = (1.0f / alpha_p[0]) * normalf(tf_bits(kn0, kn1, e));
            int qq = y - x0;
            if (qq == 0) a0 += nz; else if (qq == 1) a1 += nz;
            else if (qq == 2) a2 += nz; else a3 += nz;
        }
        float4 res = make_float4(a0, a1, a2, a3);
        *(float4*)&out[OUT_XREC + (size_t)bb * 784 + (size_t)y * 28 + x0] = res;
    }
}

// ---------------- launch ----------------
extern "C" void kernel_launch(void* const* d_in, const int* in_sizes, int n_in,
                              void* d_out, int out_size) {
    (void)in_sizes; (void)n_in; (void)out_size;
    const float* x      = (const float*)d_in[0];
    const float* enc1_w = (const float*)d_in[1];
    const float* pw1    = (const float*)d_in[2];
    const float* pw2    = (const float*)d_in[3];
    const float* enc2_w = (const float*)d_in[4];
    const float* h_w    = (const float*)d_in[5];
    const float* h_b    = (const float*)d_in[6];
    const float* mean_w = (const float*)d_in[7];
    const float* mean_b = (const float*)d_in[8];
    const float* lv_w   = (const float*)d_in[9];
    const float* lv_b   = (const float*)d_in[10];
    const float* dec2_w = (const float*)d_in[11];
    const float* dec1_w = (const float*)d_in[12];
    const float* alpha  = (const float*)d_in[13];
    float* out = (float*)d_out;

    // jax.random.key(42) = (0,42); partitionable split: key_j = tf(key, (0, j)).
    uint32_t kp0, kp1, ku0, ku1, kc0, kc1, kn0, kn1;
    tf2x32(0u, 42u, 0u, 0u, kp0, kp1);   // k_pool
    tf2x32(0u, 42u, 0u, 1u, ku0, ku1);   // k_unpool
    tf2x32(0u, 42u, 0u, 2u, kc0, kc1);   // k_code
    tf2x32(0u, 42u, 0u, 3u, kn0, kn1);   // k_noise

    k_stage1<<<B_TOT, 256>>>(x, enc1_w, pw1, pw2, out, kp0, kp1, ku0, ku1);
    k_stage2<<<B_TOT / 2, 256>>>(enc2_w, h_w, h_b, mean_w, mean_b, lv_w, lv_b,
                                 dec2_w, dec1_w, alpha, out, kc0, kc1, kn0, kn1);
}